// round 7
// baseline (speedup 1.0000x reference)
#include <cuda_runtime.h>
#include <cstdint>

// YOLOv1 loss: pred [4096,14,14,30] fp32, target same, output scalar fp32.
// R7: deep bulk-DMA ring. 1 block/SM (128 thr), 7-stage ring of 30720B
// stages in 215KB dynamic smem, prefetch depth 6 -> 184KB in flight per SM
// at all times (vs ~123KB in R5/R6). Attacks the queueing-latency ceiling.

#define NBATCH     4096
#define NCH        30
#define NCELLS     (NBATCH * 14 * 14)          // 802816
#define TILE_C     128
#define NTILES     (NCELLS / TILE_C)           // 6272 exact
#define BLOCK      128
#define NSTAGE     7
#define ARR_B      (TILE_C * NCH * 4)          // 15360 B per array
#define STAGE_B    (2 * ARR_B)                 // 30720 B
#define STAGE_F    (STAGE_B / 4)               // 7680 floats
#define SMEM_DYN   (NSTAGE * STAGE_B)          // 215040 B
#define GRID_N     148
#define DEPTH      (NSTAGE - 1)                // 6 tiles prefetched

__global__ void yolo_zero_out(float* out) {
    if (threadIdx.x == 0) out[0] = 0.0f;
}

__device__ __forceinline__ void mbar_init(uint32_t mbar, uint32_t count) {
    asm volatile("mbarrier.init.shared.b64 [%0], %1;"
                 :: "r"(mbar), "r"(count) : "memory");
}
__device__ __forceinline__ void mbar_expect_tx(uint32_t mbar, uint32_t bytes) {
    asm volatile("mbarrier.arrive.expect_tx.shared.b64 _, [%0], %1;"
                 :: "r"(mbar), "r"(bytes) : "memory");
}
__device__ __forceinline__ void bulk_g2s(uint32_t dst, const void* src,
                                         uint32_t bytes, uint32_t mbar) {
    asm volatile(
        "cp.async.bulk.shared::cluster.global.mbarrier::complete_tx::bytes "
        "[%0], [%1], %2, [%3];"
        :: "r"(dst), "l"(src), "r"(bytes), "r"(mbar) : "memory");
}
__device__ __forceinline__ void mbar_wait(uint32_t mbar, uint32_t parity) {
    asm volatile(
        "{\n\t"
        ".reg .pred P;\n\t"
        "LW%=:\n\t"
        "mbarrier.try_wait.parity.acquire.cta.shared::cta.b64 P, [%0], %1, 0x989680;\n\t"
        "@P bra LD%=;\n\t"
        "bra LW%=;\n\t"
        "LD%=:\n\t"
        "}"
        :: "r"(mbar), "r"(parity) : "memory");
}

extern __shared__ float dynbuf[];

__global__ __launch_bounds__(BLOCK)
void yolo_loss_kernel(const float* __restrict__ pred,
                      const float* __restrict__ tgt,
                      float* __restrict__ out)
{
    __shared__ uint64_t mbar_s[NSTAGE];
    __shared__ float wsum[BLOCK / 32];

    const uint32_t smem_base = (uint32_t)__cvta_generic_to_shared(dynbuf);
    const uint32_t mbar0 = (uint32_t)__cvta_generic_to_shared(mbar_s);

    if (threadIdx.x == 0) {
        #pragma unroll
        for (int s = 0; s < NSTAGE; s++) mbar_init(mbar0 + 8u * s, 1);
    }
    __syncthreads();

    // tiles for this block: blockIdx.x, +GRID_N, ... (42 or 43 tiles)
    const int n = (NTILES - blockIdx.x + GRID_N - 1) / GRID_N;

    auto issue = [&](int i) {     // issue tile i into stage i%NSTAGE
        const int tile = blockIdx.x + i * GRID_N;
        const int s = i % NSTAGE;
        const uint32_t mb  = mbar0 + 8u * s;
        const uint32_t dst = smem_base + (uint32_t)s * STAGE_B;
        mbar_expect_tx(mb, STAGE_B);
        bulk_g2s(dst,         pred + (size_t)tile * (TILE_C * NCH), ARR_B, mb);
        bulk_g2s(dst + ARR_B, tgt  + (size_t)tile * (TILE_C * NCH), ARR_B, mb);
    };

    // prologue: fill DEPTH stages (n >= 42 always)
    if (threadIdx.x == 0) {
        #pragma unroll
        for (int i = 0; i < DEPTH; i++) issue(i);
    }

    const float invS = 1.0f / 14.0f;
    float acc = 0.0f;

    for (int i = 0; i < n; i++) {
        // refill the stage freed at the end of iteration i-1
        if (threadIdx.x == 0 && (i + DEPTH) < n) issue(i + DEPTH);

        const int s = i % NSTAGE;
        mbar_wait(mbar0 + 8u * s, (uint32_t)((i / NSTAGE) & 1));

        {
            const float* p = dynbuf + s * STAGE_F + threadIdx.x * NCH;
            const float* t = p + (ARR_B / 4);

            // target box 0 (boxes are tiled identical in target)
            const float t0x = t[0], t0y = t[1], t0w = t[2], t0h = t[3];
            const float tobj = t[4];
            const float of = (tobj > 0.0f) ? 1.0f : 0.0f;

            const float tcx = t0x * invS, tcy = t0y * invS;
            const float thw = 0.5f * t0w, thh = 0.5f * t0h;
            const float tx0 = tcx - thw, tx1 = tcx + thw;
            const float ty0 = tcy - thh, ty1 = tcy + thh;
            const float area_t = t0w * t0h;

            float iou[2], px[2], py[2], pw[2], ph[2], pc[2];
            #pragma unroll
            for (int b = 0; b < 2; b++) {
                px[b] = p[5*b + 0]; py[b] = p[5*b + 1];
                pw[b] = p[5*b + 2]; ph[b] = p[5*b + 3];
                pc[b] = p[5*b + 4];
                const float pcx = px[b] * invS, pcy = py[b] * invS;
                const float phw = 0.5f * pw[b], phh = 0.5f * ph[b];
                const float px0 = pcx - phw, px1 = pcx + phw;
                const float py0 = pcy - phh, py1 = pcy + phh;
                const float ltx = fmaxf(px0, tx0), lty = fmaxf(py0, ty0);
                const float rbx = fminf(px1, tx1), rby = fminf(py1, ty1);
                const float wi = fmaxf(rbx - ltx, 0.0f);
                const float hi = fmaxf(rby - lty, 0.0f);
                const float inter = wi * hi;
                const float area_p = pw[b] * ph[b];
                iou[b] = inter / (area_p + area_t - inter);
            }

            // argmax over 2 boxes; ties -> box 0 (matches jnp.argmax)
            const int b = (iou[1] > iou[0]) ? 1 : 0;
            const float max_iou = fmaxf(iou[0], iou[1]);

            const float dx = px[b] - t0x, dy = py[b] - t0y;
            const float lxy = dx*dx + dy*dy;
            const float dw = sqrtf(pw[b]) - sqrtf(t0w);
            const float dh = sqrtf(ph[b]) - sqrtf(t0h);
            const float lwh = dw*dw + dh*dh;
            const float dob = pc[b] - max_iou;
            const float lobj = dob * dob;
            const float lno = pc[0]*pc[0] + pc[1]*pc[1]; // tgt conf=0 when no obj

            float lcls = 0.0f;
            #pragma unroll
            for (int c = 0; c < 20; c++) {
                const float d = p[10 + c] - t[10 + c];
                lcls += d * d;
            }

            acc += of * (5.0f * (lxy + lwh) + lobj + lcls)
                 + (1.0f - of) * (0.5f * lno);
        }
        __syncthreads();   // all readers done before this stage is refilled
    }

    acc *= (1.0f / (float)NBATCH);

    // warp reduce, then one atomic per block
    #pragma unroll
    for (int o = 16; o > 0; o >>= 1)
        acc += __shfl_down_sync(0xffffffffu, acc, o);
    if ((threadIdx.x & 31) == 0) wsum[threadIdx.x >> 5] = acc;
    __syncthreads();
    if (threadIdx.x == 0) {
        float ssum = 0.0f;
        #pragma unroll
        for (int w = 0; w < BLOCK / 32; w++) ssum += wsum[w];
        atomicAdd(out, ssum);
    }
}

extern "C" void kernel_launch(void* const* d_in, const int* in_sizes, int n_in,
                              void* d_out, int out_size)
{
    const float* pred = (const float*)d_in[0];
    const float* tgt  = (const float*)d_in[1];
    float* out = (float*)d_out;

    cudaFuncSetAttribute(yolo_loss_kernel,
                         cudaFuncAttributeMaxDynamicSharedMemorySize, SMEM_DYN);

    yolo_zero_out<<<1, 32>>>(out);
    yolo_loss_kernel<<<GRID_N, BLOCK, SMEM_DYN>>>(pred, tgt, out);
}

// round 8
// speedup vs baseline: 1.2713x; 1.2713x over previous
#include <cuda_runtime.h>
#include <cstdint>

// YOLOv1 loss: pred [4096,14,14,30] fp32, target same, output scalar fp32.
// R8: 2 blocks/SM x 4 warps (two independently-phased consumers per SM, the
// best-known consumer config) + 4-stage depth-3 bulk-DMA ring per block
// (TILE_C=112 -> 26880B stages, 107.5KB/block, 161KB/SM in flight).
// Single kernel: last-block-done reduction, no separate zeroing launch.

#define NBATCH     4096
#define NCH        30
#define NCELLS     (NBATCH * 14 * 14)          // 802816
#define TILE_C     112
#define NTILES     (NCELLS / TILE_C)           // 7168 exact
#define BLOCK      128
#define NSTAGE     4
#define ARR_B      (TILE_C * NCH * 4)          // 13440 B per array
#define STAGE_B    (2 * ARR_B)                 // 26880 B
#define STAGE_F    (STAGE_B / 4)               // 6720 floats
#define SMEM_DYN   (NSTAGE * STAGE_B)          // 107520 B
#define GRID_N     296                         // 2 blocks/SM
#define DEPTH      (NSTAGE - 1)                // 3 tiles prefetched

__device__ float        g_acc;     // zero-init at load; reset by last block
__device__ unsigned int g_count;

__device__ __forceinline__ void mbar_init(uint32_t mbar, uint32_t count) {
    asm volatile("mbarrier.init.shared.b64 [%0], %1;"
                 :: "r"(mbar), "r"(count) : "memory");
}
__device__ __forceinline__ void mbar_expect_tx(uint32_t mbar, uint32_t bytes) {
    asm volatile("mbarrier.arrive.expect_tx.shared.b64 _, [%0], %1;"
                 :: "r"(mbar), "r"(bytes) : "memory");
}
__device__ __forceinline__ void bulk_g2s(uint32_t dst, const void* src,
                                         uint32_t bytes, uint32_t mbar) {
    asm volatile(
        "cp.async.bulk.shared::cluster.global.mbarrier::complete_tx::bytes "
        "[%0], [%1], %2, [%3];"
        :: "r"(dst), "l"(src), "r"(bytes), "r"(mbar) : "memory");
}
__device__ __forceinline__ void mbar_wait(uint32_t mbar, uint32_t parity) {
    asm volatile(
        "{\n\t"
        ".reg .pred P;\n\t"
        "LW%=:\n\t"
        "mbarrier.try_wait.parity.acquire.cta.shared::cta.b64 P, [%0], %1, 0x989680;\n\t"
        "@P bra LD%=;\n\t"
        "bra LW%=;\n\t"
        "LD%=:\n\t"
        "}"
        :: "r"(mbar), "r"(parity) : "memory");
}

extern __shared__ float dynbuf[];

__global__ __launch_bounds__(BLOCK, 2)
void yolo_loss_kernel(const float* __restrict__ pred,
                      const float* __restrict__ tgt,
                      float* __restrict__ out)
{
    __shared__ uint64_t mbar_s[NSTAGE];
    __shared__ float wsum[BLOCK / 32];

    const uint32_t smem_base = (uint32_t)__cvta_generic_to_shared(dynbuf);
    const uint32_t mbar0 = (uint32_t)__cvta_generic_to_shared(mbar_s);

    if (threadIdx.x == 0) {
        #pragma unroll
        for (int s = 0; s < NSTAGE; s++) mbar_init(mbar0 + 8u * s, 1);
    }
    __syncthreads();

    // tiles for this block: blockIdx.x, +GRID_N, ... (24 or 25 tiles)
    const int n = (NTILES - blockIdx.x + GRID_N - 1) / GRID_N;

    auto issue = [&](int i) {     // issue tile i into stage i%NSTAGE
        const int tile = blockIdx.x + i * GRID_N;
        const int s = i % NSTAGE;
        const uint32_t mb  = mbar0 + 8u * s;
        const uint32_t dst = smem_base + (uint32_t)s * STAGE_B;
        mbar_expect_tx(mb, STAGE_B);
        bulk_g2s(dst,         pred + (size_t)tile * (TILE_C * NCH), ARR_B, mb);
        bulk_g2s(dst + ARR_B, tgt  + (size_t)tile * (TILE_C * NCH), ARR_B, mb);
    };

    if (threadIdx.x == 0) {       // n >= 24, prologue depth 3 always valid
        #pragma unroll
        for (int i = 0; i < DEPTH; i++) issue(i);
    }

    const float invS = 1.0f / 14.0f;
    float acc = 0.0f;

    for (int i = 0; i < n; i++) {
        // refill stage freed at the end of iteration i-1
        if (threadIdx.x == 0 && (i + DEPTH) < n) issue(i + DEPTH);

        const int s = i % NSTAGE;
        mbar_wait(mbar0 + 8u * s, (uint32_t)((i / NSTAGE) & 1));

        if (threadIdx.x < TILE_C) {
            const float* p = dynbuf + s * STAGE_F + threadIdx.x * NCH;
            const float* t = p + (ARR_B / 4);

            // target box 0 (boxes are tiled identical in target)
            const float t0x = t[0], t0y = t[1], t0w = t[2], t0h = t[3];
            const float tobj = t[4];
            const float of = (tobj > 0.0f) ? 1.0f : 0.0f;

            const float tcx = t0x * invS, tcy = t0y * invS;
            const float thw = 0.5f * t0w, thh = 0.5f * t0h;
            const float tx0 = tcx - thw, tx1 = tcx + thw;
            const float ty0 = tcy - thh, ty1 = tcy + thh;
            const float area_t = t0w * t0h;

            float iou[2], px[2], py[2], pw[2], ph[2], pc[2];
            #pragma unroll
            for (int b = 0; b < 2; b++) {
                px[b] = p[5*b + 0]; py[b] = p[5*b + 1];
                pw[b] = p[5*b + 2]; ph[b] = p[5*b + 3];
                pc[b] = p[5*b + 4];
                const float pcx = px[b] * invS, pcy = py[b] * invS;
                const float phw = 0.5f * pw[b], phh = 0.5f * ph[b];
                const float px0 = pcx - phw, px1 = pcx + phw;
                const float py0 = pcy - phh, py1 = pcy + phh;
                const float ltx = fmaxf(px0, tx0), lty = fmaxf(py0, ty0);
                const float rbx = fminf(px1, tx1), rby = fminf(py1, ty1);
                const float wi = fmaxf(rbx - ltx, 0.0f);
                const float hi = fmaxf(rby - lty, 0.0f);
                const float inter = wi * hi;
                const float area_p = pw[b] * ph[b];
                iou[b] = inter / (area_p + area_t - inter);
            }

            // argmax over 2 boxes; ties -> box 0 (matches jnp.argmax)
            const int b = (iou[1] > iou[0]) ? 1 : 0;
            const float max_iou = fmaxf(iou[0], iou[1]);

            const float dx = px[b] - t0x, dy = py[b] - t0y;
            const float lxy = dx*dx + dy*dy;
            const float dw = sqrtf(pw[b]) - sqrtf(t0w);
            const float dh = sqrtf(ph[b]) - sqrtf(t0h);
            const float lwh = dw*dw + dh*dh;
            const float dob = pc[b] - max_iou;
            const float lobj = dob * dob;
            const float lno = pc[0]*pc[0] + pc[1]*pc[1]; // tgt conf=0 when no obj

            float lcls = 0.0f;
            #pragma unroll
            for (int c = 0; c < 20; c++) {
                const float d = p[10 + c] - t[10 + c];
                lcls += d * d;
            }

            acc += of * (5.0f * (lxy + lwh) + lobj + lcls)
                 + (1.0f - of) * (0.5f * lno);
        }
        __syncthreads();   // all readers done before this stage is refilled
    }

    acc *= (1.0f / (float)NBATCH);

    // warp reduce, then block partial
    #pragma unroll
    for (int o = 16; o > 0; o >>= 1)
        acc += __shfl_down_sync(0xffffffffu, acc, o);
    if ((threadIdx.x & 31) == 0) wsum[threadIdx.x >> 5] = acc;
    __syncthreads();

    if (threadIdx.x == 0) {
        float ssum = 0.0f;
        #pragma unroll
        for (int w = 0; w < BLOCK / 32; w++) ssum += wsum[w];
        atomicAdd(&g_acc, ssum);
        __threadfence();
        const unsigned int done = atomicAdd(&g_count, 1u);
        if (done == GRID_N - 1) {
            // last block: publish result and reset globals for next replay
            const float total = atomicAdd(&g_acc, 0.0f);
            out[0] = total;
            atomicExch(&g_acc, 0.0f);
            atomicExch(&g_count, 0u);
        }
    }
}

extern "C" void kernel_launch(void* const* d_in, const int* in_sizes, int n_in,
                              void* d_out, int out_size)
{
    const float* pred = (const float*)d_in[0];
    const float* tgt  = (const float*)d_in[1];
    float* out = (float*)d_out;

    cudaFuncSetAttribute(yolo_loss_kernel,
                         cudaFuncAttributeMaxDynamicSharedMemorySize, SMEM_DYN);

    yolo_loss_kernel<<<GRID_N, BLOCK, SMEM_DYN>>>(pred, tgt, out);
}

// round 9
// speedup vs baseline: 1.3279x; 1.0445x over previous
#include <cuda_runtime.h>
#include <cstdint>

// YOLOv1 loss: pred [4096,14,14,30] fp32, target same, output scalar fp32.
// R9 = R5 pipeline (best known: 3-stage bulk-DMA ring, TILE_C=128, 92KB smem,
// 2 blocks/SM, prefetch depth 2) + single-kernel finalization (last-block-done
// reduction, no separate zeroing launch) proven in R8.

#define NBATCH     4096
#define NCH        30
#define NCELLS     (NBATCH * 14 * 14)          // 802816
#define TILE_C     128
#define NTILES     (NCELLS / TILE_C)           // 6272 exact
#define BLOCK      128
#define NSTAGE     3
#define ARR_B      (TILE_C * NCH * 4)          // 15360 B per array
#define STAGE_B    (2 * ARR_B)                 // 30720 B (pred+tgt)
#define STAGE_F    (STAGE_B / 4)               // 7680 floats
#define SMEM_DYN   (NSTAGE * STAGE_B)          // 92160 B
#define GRID_N     296                         // 2 blocks/SM * 148 SMs

__device__ float        g_acc;     // zero-init at load; reset by last block
__device__ unsigned int g_count;

__device__ __forceinline__ void mbar_init(uint32_t mbar, uint32_t count) {
    asm volatile("mbarrier.init.shared.b64 [%0], %1;"
                 :: "r"(mbar), "r"(count) : "memory");
}
__device__ __forceinline__ void mbar_expect_tx(uint32_t mbar, uint32_t bytes) {
    asm volatile("mbarrier.arrive.expect_tx.shared.b64 _, [%0], %1;"
                 :: "r"(mbar), "r"(bytes) : "memory");
}
__device__ __forceinline__ void bulk_g2s(uint32_t dst, const void* src,
                                         uint32_t bytes, uint32_t mbar) {
    asm volatile(
        "cp.async.bulk.shared::cluster.global.mbarrier::complete_tx::bytes "
        "[%0], [%1], %2, [%3];"
        :: "r"(dst), "l"(src), "r"(bytes), "r"(mbar) : "memory");
}
__device__ __forceinline__ void mbar_wait(uint32_t mbar, uint32_t parity) {
    asm volatile(
        "{\n\t"
        ".reg .pred P;\n\t"
        "LW%=:\n\t"
        "mbarrier.try_wait.parity.acquire.cta.shared::cta.b64 P, [%0], %1, 0x989680;\n\t"
        "@P bra LD%=;\n\t"
        "bra LW%=;\n\t"
        "LD%=:\n\t"
        "}"
        :: "r"(mbar), "r"(parity) : "memory");
}

extern __shared__ float dynbuf[];

__global__ __launch_bounds__(BLOCK)
void yolo_loss_kernel(const float* __restrict__ pred,
                      const float* __restrict__ tgt,
                      float* __restrict__ out)
{
    __shared__ uint64_t mbar_s[NSTAGE];
    __shared__ float wsum[BLOCK / 32];

    const uint32_t smem_base = (uint32_t)__cvta_generic_to_shared(dynbuf);
    const uint32_t mbar0 = (uint32_t)__cvta_generic_to_shared(mbar_s);

    if (threadIdx.x == 0) {
        #pragma unroll
        for (int s = 0; s < NSTAGE; s++) mbar_init(mbar0 + 8u * s, 1);
    }
    __syncthreads();

    // this block's tile count: tiles are blockIdx.x, +GRID_N, ... (21 or 22)
    const int n = (NTILES - blockIdx.x + GRID_N - 1) / GRID_N;

    // issue tile i into stage i%NSTAGE
    auto issue = [&](int i) {
        const int tile = blockIdx.x + i * GRID_N;
        const int s = i % NSTAGE;
        const uint32_t mb = mbar0 + 8u * s;
        const uint32_t dst = smem_base + (uint32_t)s * STAGE_B;
        mbar_expect_tx(mb, STAGE_B);
        bulk_g2s(dst,         pred + (size_t)tile * (TILE_C * NCH), ARR_B, mb);
        bulk_g2s(dst + ARR_B, tgt  + (size_t)tile * (TILE_C * NCH), ARR_B, mb);
    };

    // prologue: prefetch depth 2 (n >= 21 always)
    if (threadIdx.x == 0) {
        issue(0);
        issue(1);
    }

    const float invS = 1.0f / 14.0f;
    float acc = 0.0f;

    for (int i = 0; i < n; i++) {
        // refill stage (i+2)%NSTAGE: its previous tile (i-1) finished at the
        // __syncthreads() that ended iteration i-1.
        if (threadIdx.x == 0 && (i + 2) < n) issue(i + 2);

        const int s = i % NSTAGE;
        mbar_wait(mbar0 + 8u * s, (uint32_t)((i / NSTAGE) & 1));

        {
            const float* p = dynbuf + s * STAGE_F + threadIdx.x * NCH;
            const float* t = p + (ARR_B / 4);

            // target box 0 (boxes are tiled identical in target)
            const float t0x = t[0], t0y = t[1], t0w = t[2], t0h = t[3];
            const float tobj = t[4];
            const float of = (tobj > 0.0f) ? 1.0f : 0.0f;

            const float tcx = t0x * invS, tcy = t0y * invS;
            const float thw = 0.5f * t0w, thh = 0.5f * t0h;
            const float tx0 = tcx - thw, tx1 = tcx + thw;
            const float ty0 = tcy - thh, ty1 = tcy + thh;
            const float area_t = t0w * t0h;

            float iou[2], px[2], py[2], pw[2], ph[2], pc[2];
            #pragma unroll
            for (int b = 0; b < 2; b++) {
                px[b] = p[5*b + 0]; py[b] = p[5*b + 1];
                pw[b] = p[5*b + 2]; ph[b] = p[5*b + 3];
                pc[b] = p[5*b + 4];
                const float pcx = px[b] * invS, pcy = py[b] * invS;
                const float phw = 0.5f * pw[b], phh = 0.5f * ph[b];
                const float px0 = pcx - phw, px1 = pcx + phw;
                const float py0 = pcy - phh, py1 = pcy + phh;
                const float ltx = fmaxf(px0, tx0), lty = fmaxf(py0, ty0);
                const float rbx = fminf(px1, tx1), rby = fminf(py1, ty1);
                const float wi = fmaxf(rbx - ltx, 0.0f);
                const float hi = fmaxf(rby - lty, 0.0f);
                const float inter = wi * hi;
                const float area_p = pw[b] * ph[b];
                iou[b] = inter / (area_p + area_t - inter);
            }

            // argmax over 2 boxes; ties -> box 0 (matches jnp.argmax)
            const int b = (iou[1] > iou[0]) ? 1 : 0;
            const float max_iou = fmaxf(iou[0], iou[1]);

            const float dx = px[b] - t0x, dy = py[b] - t0y;
            const float lxy = dx*dx + dy*dy;
            const float dw = sqrtf(pw[b]) - sqrtf(t0w);
            const float dh = sqrtf(ph[b]) - sqrtf(t0h);
            const float lwh = dw*dw + dh*dh;
            const float dob = pc[b] - max_iou;
            const float lobj = dob * dob;
            const float lno = pc[0]*pc[0] + pc[1]*pc[1]; // tgt conf=0 when no obj

            float lcls = 0.0f;
            #pragma unroll
            for (int c = 0; c < 20; c++) {
                const float d = p[10 + c] - t[10 + c];
                lcls += d * d;
            }

            acc += of * (5.0f * (lxy + lwh) + lobj + lcls)
                 + (1.0f - of) * (0.5f * lno);
        }
        __syncthreads();   // all readers done before stage is refilled
    }

    acc *= (1.0f / (float)NBATCH);

    // warp reduce, then block partial
    #pragma unroll
    for (int o = 16; o > 0; o >>= 1)
        acc += __shfl_down_sync(0xffffffffu, acc, o);
    if ((threadIdx.x & 31) == 0) wsum[threadIdx.x >> 5] = acc;
    __syncthreads();

    if (threadIdx.x == 0) {
        float ssum = 0.0f;
        #pragma unroll
        for (int w = 0; w < BLOCK / 32; w++) ssum += wsum[w];
        atomicAdd(&g_acc, ssum);
        __threadfence();
        const unsigned int done = atomicAdd(&g_count, 1u);
        if (done == GRID_N - 1) {
            // last block: publish result and reset globals for next replay
            const float total = atomicAdd(&g_acc, 0.0f);
            out[0] = total;
            atomicExch(&g_acc, 0.0f);
            atomicExch(&g_count, 0u);
        }
    }
}

extern "C" void kernel_launch(void* const* d_in, const int* in_sizes, int n_in,
                              void* d_out, int out_size)
{
    const float* pred = (const float*)d_in[0];
    const float* tgt  = (const float*)d_in[1];
    float* out = (float*)d_out;

    cudaFuncSetAttribute(yolo_loss_kernel,
                         cudaFuncAttributeMaxDynamicSharedMemorySize, SMEM_DYN);

    yolo_loss_kernel<<<GRID_N, BLOCK, SMEM_DYN>>>(pred, tgt, out);
}